// round 11
// baseline (speedup 1.0000x reference)
#include <cuda_runtime.h>
#include <math.h>

#define B_  32
#define C_  256
#define H_  128
#define W_  128
#define HW  (H_ * W_)
#define HW4 (HW / 4)

#define PDL_LAUNCH_DEPENDENTS() asm volatile("griddepcontrol.launch_dependents;" ::: "memory")
#define PDL_WAIT()              asm volatile("griddepcontrol.wait;" ::: "memory")

__device__ float g_avg [B_ * HW];
__device__ float g_max [B_ * HW];
__device__ float g_gate[B_ * HW];

// ---------------------------------------------------------------------------
// K1: channel-wise mean & max over y. NSPLIT=2 half-block combine:
// threadIdx>>7 = channel half, threadIdx&127 = quad. Every warp issues one
// 512B fully-contiguous load per channel (R2's proven 6.8TB/s pattern); only
// 4KB smem + one sync; writes only the final 8MB.
// ---------------------------------------------------------------------------
__global__ void __launch_bounds__(256) reduce_kernel(const float* __restrict__ y) {
    __shared__ float4 s_s[128];
    __shared__ float4 s_m[128];

    int t    = threadIdx.x & 127;         // quad within block
    int half = threadIdx.x >> 7;          // channel half (128 ch each)
    int q    = blockIdx.x * 128 + t;      // global pixel-quad
    int b    = q >> 12;                   // / HW4 (4096); 4096%128==0, no cross
    int p4   = q & 4095;

    const float4* base = reinterpret_cast<const float4*>(y)
                       + ((size_t)b * C_ + (size_t)half * 128) * HW4 + p4;

    float4 s = make_float4(0.f, 0.f, 0.f, 0.f);
    float4 m = make_float4(-INFINITY, -INFINITY, -INFINITY, -INFINITY);

    #pragma unroll 8
    for (int c = 0; c < 128; c++) {
        float4 v = __ldcs(base + (size_t)c * HW4);
        s.x += v.x; s.y += v.y; s.z += v.z; s.w += v.w;
        m.x = fmaxf(m.x, v.x); m.y = fmaxf(m.y, v.y);
        m.z = fmaxf(m.z, v.z); m.w = fmaxf(m.w, v.w);
    }

    if (half == 1) {
        s_s[t] = s;
        s_m[t] = m;
    }
    __syncthreads();

    PDL_LAUNCH_DEPENDENTS();

    if (half == 0) {
        float4 ts = s_s[t];
        float4 tm = s_m[t];
        s.x += ts.x; s.y += ts.y; s.z += ts.z; s.w += ts.w;
        m.x = fmaxf(m.x, tm.x); m.y = fmaxf(m.y, tm.y);
        m.z = fmaxf(m.z, tm.z); m.w = fmaxf(m.w, tm.w);
        const float inv = 1.0f / (float)C_;
        s.x *= inv; s.y *= inv; s.z *= inv; s.w *= inv;
        reinterpret_cast<float4*>(g_avg)[q] = s;
        reinterpret_cast<float4*>(g_max)[q] = m;
    }
}

// ---------------------------------------------------------------------------
// K2: 3x3 conv + sigmoid -> gate. smem-tiled 32x32 with 34x34 halo. PDL both
// directions. (Identical to R8.)
// ---------------------------------------------------------------------------
__global__ void __launch_bounds__(256) gate_kernel(const float* __restrict__ conv_w) {
    __shared__ float s_avg[34][36];
    __shared__ float s_max[34][36];

    int blk = blockIdx.x;
    int b  = blk >> 4;
    int r  = blk & 15;
    int th = r >> 2;
    int tw = r & 3;
    int h0 = th * 32 - 1;
    int w0 = tw * 32 - 1;

    float wa[9], wm[9];
    #pragma unroll
    for (int k = 0; k < 9; k++) { wa[k] = conv_w[k]; wm[k] = conv_w[9 + k]; }

    PDL_WAIT();

    for (int i = threadIdx.x; i < 34 * 34; i += 256) {
        int lh = i / 34;
        int lw = i - lh * 34;
        int h  = h0 + lh;
        int w  = w0 + lw;
        float a = 0.f, m = 0.f;
        if (h >= 0 && h < H_ && w >= 0 && w < W_) {
            int si = b * HW + h * W_ + w;
            a = g_avg[si];
            m = g_max[si];
        }
        s_avg[lh][lw] = a;
        s_max[lh][lw] = m;
    }
    __syncthreads();

    PDL_LAUNCH_DEPENDENTS();

    for (int i = threadIdx.x; i < 32 * 32; i += 256) {
        int lh = i >> 5;
        int lw = i & 31;
        float acc = 0.f;
        #pragma unroll
        for (int kh = 0; kh < 3; kh++)
            #pragma unroll
            for (int kw = 0; kw < 3; kw++) {
                acc = fmaf(s_avg[lh + kh][lw + kw], wa[kh * 3 + kw], acc);
                acc = fmaf(s_max[lh + kh][lw + kw], wm[kh * 3 + kw], acc);
            }
        int h = th * 32 + lh;
        int w = tw * 32 + lw;
        g_gate[b * HW + h * W_ + w] = 1.0f / (1.0f + expf(-acc));
    }
}

// ---------------------------------------------------------------------------
// K3: out = x * gate (R5/R8 2-pair form). x loads before PDL wait.
// ---------------------------------------------------------------------------
__global__ void __launch_bounds__(256) mul_kernel(const float* __restrict__ x,
                                                  float* __restrict__ out) {
    int plane = blockIdx.y;                    // b*C + c
    int b     = plane >> 8;
    int p4    = blockIdx.x * 512 + threadIdx.x;

    size_t base = (size_t)plane * HW4;
    const float4* xin = reinterpret_cast<const float4*>(x)   + base;
    float4*       dst = reinterpret_cast<float4*>(out)       + base;
    const float4* gp  = reinterpret_cast<const float4*>(g_gate) + (size_t)b * HW4;

    float4 x0  = __ldcs(xin + p4);
    float4 x1  = __ldcs(xin + p4 + 256);

    PDL_WAIT();

    float4 g0  = __ldg(gp + p4);
    float4 g1  = __ldg(gp + p4 + 256);

    float4 o0, o1;
    o0.x = x0.x * g0.x; o0.y = x0.y * g0.y; o0.z = x0.z * g0.z; o0.w = x0.w * g0.w;
    o1.x = x1.x * g1.x; o1.y = x1.y * g1.y; o1.z = x1.z * g1.z; o1.w = x1.w * g1.w;

    __stcs(dst + p4,       o0);
    __stcs(dst + p4 + 256, o1);
}

// ---------------------------------------------------------------------------
static void launch_pdl(void* func, dim3 grid, dim3 block, void** args) {
    cudaLaunchConfig_t cfg = {};
    cfg.gridDim  = grid;
    cfg.blockDim = block;
    cfg.dynamicSmemBytes = 0;
    cfg.stream = 0;
    cudaLaunchAttribute attr[1];
    attr[0].id = cudaLaunchAttributeProgrammaticStreamSerialization;
    attr[0].val.programmaticStreamSerializationAllowed = 1;
    cfg.attrs = attr;
    cfg.numAttrs = 1;
    cudaLaunchKernelExC(&cfg, func, args);
}

extern "C" void kernel_launch(void* const* d_in, const int* in_sizes, int n_in,
                              void* d_out, int out_size) {
    const float* x      = (const float*)d_in[0];
    const float* y      = (const float*)d_in[1];
    const float* conv_w = (const float*)d_in[2];
    float* out          = (float*)d_out;

    reduce_kernel<<<B_ * HW4 / 128, 256>>>(y);       // 1024 blocks

    {
        void* args[] = { (void*)&conv_w };
        launch_pdl((void*)gate_kernel, dim3(B_ * 16), dim3(256), args);
    }
    {
        void* args[] = { (void*)&x, (void*)&out };
        launch_pdl((void*)mul_kernel, dim3(HW4 / 512, B_ * C_), dim3(256), args);
    }
}

// round 12
// speedup vs baseline: 1.0147x; 1.0147x over previous
#include <cuda_runtime.h>
#include <math.h>

#define B_  32
#define C_  256
#define H_  128
#define W_  128
#define HW  (H_ * W_)
#define HW4 (HW / 4)
#define NSPLIT 8

#define PDL_LAUNCH_DEPENDENTS() asm volatile("griddepcontrol.launch_dependents;" ::: "memory")
#define PDL_WAIT()              asm volatile("griddepcontrol.wait;" ::: "memory")

__device__ float g_avg [B_ * HW];
__device__ float g_max [B_ * HW];
__device__ float g_gate[B_ * HW];

// ---------------------------------------------------------------------------
// K1: channel-wise mean & max over y (R5/R8 form — best total measured).
// Block = 8 channel-parts x 32 pixel-quads, smem combine, writes only 8 MB.
// launch_dependents at the tail so K2 spins up while the last wave drains.
// ---------------------------------------------------------------------------
__global__ void __launch_bounds__(256) reduce_kernel(const float* __restrict__ y) {
    __shared__ float4 s_s[NSPLIT][32];
    __shared__ float4 s_m[NSPLIT][32];

    int lane = threadIdx.x & 31;
    int part = threadIdx.x >> 5;
    int q    = blockIdx.x * 32 + lane;
    int b    = q >> 12;
    int p4   = q & 4095;

    const float4* base = reinterpret_cast<const float4*>(y)
                       + ((size_t)b * C_ + (size_t)part * (C_ / NSPLIT)) * HW4 + p4;

    float4 s = make_float4(0.f, 0.f, 0.f, 0.f);
    float4 m = make_float4(-INFINITY, -INFINITY, -INFINITY, -INFINITY);

    #pragma unroll 8
    for (int c = 0; c < C_ / NSPLIT; c++) {
        float4 v = __ldcs(base + (size_t)c * HW4);
        s.x += v.x; s.y += v.y; s.z += v.z; s.w += v.w;
        m.x = fmaxf(m.x, v.x); m.y = fmaxf(m.y, v.y);
        m.z = fmaxf(m.z, v.z); m.w = fmaxf(m.w, v.w);
    }

    s_s[part][lane] = s;
    s_m[part][lane] = m;
    __syncthreads();

    PDL_LAUNCH_DEPENDENTS();      // tail: main loop done for this CTA

    if (part == 0) {
        #pragma unroll
        for (int p = 1; p < NSPLIT; p++) {
            float4 t  = s_s[p][lane];
            float4 tm = s_m[p][lane];
            s.x += t.x; s.y += t.y; s.z += t.z; s.w += t.w;
            m.x = fmaxf(m.x, tm.x); m.y = fmaxf(m.y, tm.y);
            m.z = fmaxf(m.z, tm.z); m.w = fmaxf(m.w, tm.w);
        }
        const float inv = 1.0f / (float)C_;
        s.x *= inv; s.y *= inv; s.z *= inv; s.w *= inv;
        reinterpret_cast<float4*>(g_avg)[q] = s;
        reinterpret_cast<float4*>(g_max)[q] = m;
    }
}

// ---------------------------------------------------------------------------
// K2: 3x3 conv + sigmoid -> gate. PDL: loads conv_w (independent) before the
// wait; reads g_avg/g_max only after. launch_dependents at tail for K3.
// ---------------------------------------------------------------------------
__global__ void __launch_bounds__(256) gate_kernel(const float* __restrict__ conv_w) {
    __shared__ float s_avg[34][36];
    __shared__ float s_max[34][36];

    int blk = blockIdx.x;
    int b  = blk >> 4;
    int r  = blk & 15;
    int th = r >> 2;
    int tw = r & 3;
    int h0 = th * 32 - 1;
    int w0 = tw * 32 - 1;

    // Independent of K1: weights.
    float wa[9], wm[9];
    #pragma unroll
    for (int k = 0; k < 9; k++) { wa[k] = conv_w[k]; wm[k] = conv_w[9 + k]; }

    PDL_WAIT();                   // K1's g_avg/g_max now visible

    for (int i = threadIdx.x; i < 34 * 34; i += 256) {
        int lh = i / 34;
        int lw = i - lh * 34;
        int h  = h0 + lh;
        int w  = w0 + lw;
        float a = 0.f, m = 0.f;
        if (h >= 0 && h < H_ && w >= 0 && w < W_) {
            int si = b * HW + h * W_ + w;
            a = g_avg[si];
            m = g_max[si];
        }
        s_avg[lh][lw] = a;
        s_max[lh][lw] = m;
    }
    __syncthreads();

    PDL_LAUNCH_DEPENDENTS();

    for (int i = threadIdx.x; i < 32 * 32; i += 256) {
        int lh = i >> 5;
        int lw = i & 31;
        float acc = 0.f;
        #pragma unroll
        for (int kh = 0; kh < 3; kh++)
            #pragma unroll
            for (int kw = 0; kw < 3; kw++) {
                acc = fmaf(s_avg[lh + kh][lw + kw], wa[kh * 3 + kw], acc);
                acc = fmaf(s_max[lh + kh][lw + kw], wm[kh * 3 + kw], acc);
            }
        int h = th * 32 + lh;
        int w = tw * 32 + lw;
        g_gate[b * HW + h * W_ + w] = 1.0f / (1.0f + expf(-acc));
    }
}

// ---------------------------------------------------------------------------
// K3: out = x * gate (R5 2-pair form — best measured). PDL: x loads issued
// before the wait (independent of gate); gate loads after.
// ---------------------------------------------------------------------------
__global__ void __launch_bounds__(256) mul_kernel(const float* __restrict__ x,
                                                  float* __restrict__ out) {
    int plane = blockIdx.y;                    // b*C + c
    int b     = plane >> 8;
    int p4    = blockIdx.x * 512 + threadIdx.x;

    size_t base = (size_t)plane * HW4;
    const float4* xin = reinterpret_cast<const float4*>(x)   + base;
    float4*       dst = reinterpret_cast<float4*>(out)       + base;
    const float4* gp  = reinterpret_cast<const float4*>(g_gate) + (size_t)b * HW4;

    // Independent of K2: x stream.
    float4 x0  = __ldcs(xin + p4);
    float4 x1  = __ldcs(xin + p4 + 256);

    PDL_WAIT();                   // gate now visible

    float4 g0  = __ldg(gp + p4);
    float4 g1  = __ldg(gp + p4 + 256);

    float4 o0, o1;
    o0.x = x0.x * g0.x; o0.y = x0.y * g0.y; o0.z = x0.z * g0.z; o0.w = x0.w * g0.w;
    o1.x = x1.x * g1.x; o1.y = x1.y * g1.y; o1.z = x1.z * g1.z; o1.w = x1.w * g1.w;

    __stcs(dst + p4,       o0);
    __stcs(dst + p4 + 256, o1);
}

// ---------------------------------------------------------------------------
static void launch_pdl(void* func, dim3 grid, dim3 block, void** args) {
    cudaLaunchConfig_t cfg = {};
    cfg.gridDim  = grid;
    cfg.blockDim = block;
    cfg.dynamicSmemBytes = 0;
    cfg.stream = 0;               // legacy default stream (captured)
    cudaLaunchAttribute attr[1];
    attr[0].id = cudaLaunchAttributeProgrammaticStreamSerialization;
    attr[0].val.programmaticStreamSerializationAllowed = 1;
    cfg.attrs = attr;
    cfg.numAttrs = 1;
    cudaLaunchKernelExC(&cfg, func, args);
}

extern "C" void kernel_launch(void* const* d_in, const int* in_sizes, int n_in,
                              void* d_out, int out_size) {
    const float* x      = (const float*)d_in[0];
    const float* y      = (const float*)d_in[1];
    const float* conv_w = (const float*)d_in[2];
    float* out          = (float*)d_out;

    reduce_kernel<<<B_ * HW4 / 32, 256>>>(y);        // 4096 blocks (R5 form)

    {
        void* args[] = { (void*)&conv_w };
        launch_pdl((void*)gate_kernel, dim3(B_ * 16), dim3(256), args);
    }
    {
        void* args[] = { (void*)&x, (void*)&out };
        launch_pdl((void*)mul_kernel, dim3(HW4 / 512, B_ * C_), dim3(256), args);
    }
}